// round 1
// baseline (speedup 1.0000x reference)
#include <cuda_runtime.h>
#include <math.h>

#define Bn    4
#define SEQ   4096
#define Ein   2048
#define HD    2048
#define HEADS 16
#define DHd   128
#define MR    (Bn * SEQ)      // 16384 rows
#define SPLITS 4

// ---------------- scratch (device globals; no allocation allowed) ----------------
__device__ float g_q [MR * HD];                       // elu(x@Wqk + bqk)   134 MB
__device__ float g_v [MR * HD];                       // silu(x@Wv + bv)    134 MB
__device__ float g_u [MR * HD];                       // silu(x@Wu + bu)    134 MB
__device__ float g_o [MR * HD];                       // attention out / LN 134 MB
__device__ float g_kv[SPLITS * Bn * HEADS * DHd * DHd]; // split-k kv slices  16 MB

// ---------------- fused GEMM + bias + activation (128x128x8 fp32) ----------------
// ACT: 0 = none, 1 = elu, 2 = silu
template<int ACT>
__global__ void gemm_bias_act(const float* __restrict__ A, const float* __restrict__ W,
                              const float* __restrict__ bias, float* __restrict__ C,
                              int M, int N, int K) {
    __shared__ float As[8][128];
    __shared__ float Bs[8][128];
    const int tid = threadIdx.x;
    const int m0 = blockIdx.y * 128;
    const int n0 = blockIdx.x * 128;
    const int tx = tid & 15, ty = tid >> 4;

    float acc[8][8] = {};

    const int a_row = tid >> 1;
    const int a_seg = (tid & 1) * 4;
    const int b_row = tid >> 5;
    const int b_col = (tid & 31) * 4;
    const float* Aptr = A + (size_t)(m0 + a_row) * K + a_seg;
    const float* Wptr = W + (size_t)b_row * N + n0 + b_col;

    for (int k0 = 0; k0 < K; k0 += 8) {
        float4 av = *(const float4*)(Aptr + k0);
        As[a_seg + 0][a_row] = av.x;
        As[a_seg + 1][a_row] = av.y;
        As[a_seg + 2][a_row] = av.z;
        As[a_seg + 3][a_row] = av.w;
        *(float4*)&Bs[b_row][b_col] = *(const float4*)(Wptr + (size_t)k0 * N);
        __syncthreads();
#pragma unroll
        for (int kk = 0; kk < 8; kk++) {
            float ra[8], rb[8];
#pragma unroll
            for (int i = 0; i < 8; i++) ra[i] = As[kk][ty * 8 + i];
#pragma unroll
            for (int j = 0; j < 8; j++) rb[j] = Bs[kk][tx * 8 + j];
#pragma unroll
            for (int i = 0; i < 8; i++)
#pragma unroll
                for (int j = 0; j < 8; j++)
                    acc[i][j] += ra[i] * rb[j];
        }
        __syncthreads();
    }

#pragma unroll
    for (int i = 0; i < 8; i++) {
        const int row = m0 + ty * 8 + i;
#pragma unroll
        for (int j = 0; j < 8; j += 4) {
            float4 o;
            float* po = &o.x;
#pragma unroll
            for (int t = 0; t < 4; t++) {
                const int col = n0 + tx * 8 + j + t;
                float v = acc[i][j + t] + bias[col];
                if (ACT == 1)      v = v > 0.f ? v : (expf(v) - 1.f);
                else if (ACT == 2) v = v / (1.f + expf(-v));
                po[t] = v;
            }
            *(float4*)(C + (size_t)row * N + n0 + tx * 8 + j) = o;
        }
    }
}

// ---------------- kv = k^T v  per (b,h), split-k over sequence ----------------
// grid (B*HEADS, SPLITS), 256 threads. Output: g_kv[split][bh][128][128]
__global__ void kv_kernel() {
    __shared__ float qs[16][128];
    __shared__ float vs[16][128];
    const int bh = blockIdx.x;
    const int b = bh / HEADS, h = bh % HEADS;
    const int split = blockIdx.y;
    const int chunk = SEQ / SPLITS;     // 1024
    const int n0 = split * chunk;
    const int tid = threadIdx.x;
    const int tx = tid & 15, ty = tid >> 4;
    const size_t base = (size_t)(b * SEQ) * HD + h * DHd;

    float acc[8][8] = {};

    for (int nt = 0; nt < chunk; nt += 16) {
#pragma unroll
        for (int l = 0; l < 2; l++) {
            const int idx = tid + l * 256;
            const int r = idx >> 5;
            const int c = (idx & 31) * 4;
            const size_t off = base + (size_t)(n0 + nt + r) * HD + c;
            *(float4*)&qs[r][c] = *(const float4*)(g_q + off);
            *(float4*)&vs[r][c] = *(const float4*)(g_v + off);
        }
        __syncthreads();
#pragma unroll
        for (int kk = 0; kk < 16; kk++) {
            float rq[8], rv[8];
#pragma unroll
            for (int i = 0; i < 8; i++) rq[i] = qs[kk][ty * 8 + i];
#pragma unroll
            for (int j = 0; j < 8; j++) rv[j] = vs[kk][tx * 8 + j];
#pragma unroll
            for (int i = 0; i < 8; i++)
#pragma unroll
                for (int j = 0; j < 8; j++)
                    acc[i][j] += rq[i] * rv[j];
        }
        __syncthreads();
    }

    float* kvp = g_kv + ((size_t)split * Bn * HEADS + bh) * DHd * DHd;
#pragma unroll
    for (int i = 0; i < 8; i++)
#pragma unroll
        for (int j = 0; j < 8; j++)
            kvp[(ty * 8 + i) * DHd + tx * 8 + j] = acc[i][j];
}

// ---------------- out = q @ kv  per (b,h) --------------------------------------
// grid (MR/64, HEADS), 256 threads. 64x128 tile, K = 128. Sums 4 split slices.
__global__ void out_kernel() {
    __shared__ float As[16][64];
    __shared__ float Bs[16][128];
    const int m0 = blockIdx.x * 64;
    const int h = blockIdx.y;
    const int b = m0 / SEQ;
    const int tid = threadIdx.x;
    const int tx = tid & 15, ty = tid >> 4;
    const size_t kvoff = (size_t)(b * HEADS + h) * DHd * DHd;
    const size_t kvstride = (size_t)Bn * HEADS * DHd * DHd;

    float acc[4][8] = {};

    const int a_r = tid >> 2;
    const int a_s = (tid & 3) * 4;

    for (int k0 = 0; k0 < DHd; k0 += 16) {
        float4 av = *(const float4*)(g_q + (size_t)(m0 + a_r) * HD + h * DHd + k0 + a_s);
        As[a_s + 0][a_r] = av.x;
        As[a_s + 1][a_r] = av.y;
        As[a_s + 2][a_r] = av.z;
        As[a_s + 3][a_r] = av.w;
#pragma unroll
        for (int l = 0; l < 2; l++) {
            const int idx = tid + l * 256;
            const int r = idx >> 5;
            const int c = (idx & 31) * 4;
            const size_t boff = kvoff + (size_t)(k0 + r) * DHd + c;
            float4 s0 = *(const float4*)(g_kv + boff);
            float4 s1 = *(const float4*)(g_kv + boff + kvstride);
            float4 s2 = *(const float4*)(g_kv + boff + 2 * kvstride);
            float4 s3 = *(const float4*)(g_kv + boff + 3 * kvstride);
            float4 sum;
            sum.x = (s0.x + s1.x) + (s2.x + s3.x);
            sum.y = (s0.y + s1.y) + (s2.y + s3.y);
            sum.z = (s0.z + s1.z) + (s2.z + s3.z);
            sum.w = (s0.w + s1.w) + (s2.w + s3.w);
            *(float4*)&Bs[r][c] = sum;
        }
        __syncthreads();
#pragma unroll
        for (int kk = 0; kk < 16; kk++) {
            float ra[4], rb[8];
#pragma unroll
            for (int i = 0; i < 4; i++) ra[i] = As[kk][ty * 4 + i];
#pragma unroll
            for (int j = 0; j < 8; j++) rb[j] = Bs[kk][tx * 8 + j];
#pragma unroll
            for (int i = 0; i < 4; i++)
#pragma unroll
                for (int j = 0; j < 8; j++)
                    acc[i][j] += ra[i] * rb[j];
        }
        __syncthreads();
    }

#pragma unroll
    for (int i = 0; i < 4; i++)
#pragma unroll
        for (int j = 0; j < 8; j++)
            g_o[(size_t)(m0 + ty * 4 + i) * HD + h * DHd + tx * 8 + j] = acc[i][j];
}

// ---------------- LayerNorm over HD, then multiply by gate u (in place on g_o) --
__global__ void ln_mul_kernel(const float* __restrict__ lng, const float* __restrict__ lnb) {
    __shared__ float buf[HD];
    __shared__ float red[256];
    const int row = blockIdx.x;
    const int tid = threadIdx.x;
    float* orow = g_o + (size_t)row * HD;
    const float* urow = g_u + (size_t)row * HD;

    float s = 0.f;
    for (int c = tid; c < HD; c += 256) { float v = orow[c]; buf[c] = v; s += v; }
    red[tid] = s; __syncthreads();
    for (int off = 128; off; off >>= 1) { if (tid < off) red[tid] += red[tid + off]; __syncthreads(); }
    const float mean = red[0] * (1.f / HD);
    __syncthreads();

    float s2 = 0.f;
    for (int c = tid; c < HD; c += 256) { float d = buf[c] - mean; s2 += d * d; }
    red[tid] = s2; __syncthreads();
    for (int off = 128; off; off >>= 1) { if (tid < off) red[tid] += red[tid + off]; __syncthreads(); }
    const float rstd = rsqrtf(red[0] * (1.f / HD) + 1e-5f);

    for (int c = tid; c < HD; c += 256) {
        float v = (buf[c] - mean) * rstd * lng[c] + lnb[c];
        orow[c] = v * urow[c];
    }
}

// ---------------- launch ---------------------------------------------------------
extern "C" void kernel_launch(void* const* d_in, const int* in_sizes, int n_in,
                              void* d_out, int out_size) {
    const float* x   = (const float*)d_in[0];
    const float* Wqk = (const float*)d_in[1];
    const float* bqk = (const float*)d_in[2];
    const float* Wv  = (const float*)d_in[3];
    const float* bv  = (const float*)d_in[4];
    const float* Wu  = (const float*)d_in[5];
    const float* bu  = (const float*)d_in[6];
    const float* Wo  = (const float*)d_in[7];
    const float* bo  = (const float*)d_in[8];
    const float* lng = (const float*)d_in[9];
    const float* lnb = (const float*)d_in[10];
    float* out = (float*)d_out;

    float *pq, *pv, *pu, *po;
    cudaGetSymbolAddress((void**)&pq, g_q);
    cudaGetSymbolAddress((void**)&pv, g_v);
    cudaGetSymbolAddress((void**)&pu, g_u);
    cudaGetSymbolAddress((void**)&po, g_o);

    dim3 gThreads(256);
    dim3 gGrid(HD / 128, MR / 128);       // (16, 128)

    // q = elu(x @ Wqk + bqk)  (k is identical to q)
    gemm_bias_act<1><<<gGrid, gThreads>>>(x, Wqk, bqk, pq, MR, HD, Ein);
    // v = silu(x @ Wv + bv)
    gemm_bias_act<2><<<gGrid, gThreads>>>(x, Wv, bv, pv, MR, HD, Ein);
    // u = silu(x @ Wu + bu)
    gemm_bias_act<2><<<gGrid, gThreads>>>(x, Wu, bu, pu, MR, HD, Ein);

    // kv = q^T v per (b,h), split over sequence (deterministic: separate slices)
    kv_kernel<<<dim3(Bn * HEADS, SPLITS), 256>>>();

    // o = q @ kv per (b,h)
    out_kernel<<<dim3(MR / 64, HEADS), 256>>>();

    // o = layernorm(o) * u   (in place)
    ln_mul_kernel<<<MR, 256>>>(lng, lnb);

    // y = o @ Wo + bo
    gemm_bias_act<0><<<gGrid, gThreads>>>(po, Wo, bo, out, MR, Ein, HD);
}

// round 5
// speedup vs baseline: 3.6300x; 3.6300x over previous
#include <cuda_runtime.h>
#include <cuda_bf16.h>
#include <cstdint>
#include <math.h>

#define Bn    4
#define SEQ   4096
#define Ein   2048
#define HD    2048
#define HEADS 16
#define DHd   128
#define MR    (Bn * SEQ)      // 16384
#define SPLITS 4

// ---------------------------------------------------------------------------
// PTX helpers (base-target safe: sm_80+ instructions only)
// ---------------------------------------------------------------------------
__device__ __forceinline__ uint32_t smem_u32(const void* p) {
    uint32_t a;
    asm("{ .reg .u64 t; cvta.to.shared.u64 t, %1; cvt.u32.u64 %0, t; }" : "=r"(a) : "l"(p));
    return a;
}

#define CP16(dst, src) \
    asm volatile("cp.async.cg.shared.global [%0], [%1], 16;" :: "r"(dst), "l"(src) : "memory")
#define CP_COMMIT() asm volatile("cp.async.commit_group;" ::: "memory")
#define CP_WAIT(n)  asm volatile("cp.async.wait_group %0;" :: "n"(n) : "memory")

#define LDMX4(r, addr) \
    asm volatile("ldmatrix.sync.aligned.m8n8.x4.shared.b16 {%0,%1,%2,%3}, [%4];" \
        : "=r"((r)[0]), "=r"((r)[1]), "=r"((r)[2]), "=r"((r)[3]) : "r"(addr))

#define MMA_TF32(d, a, b0v, b1v) \
    asm volatile("mma.sync.aligned.m16n8k8.row.col.f32.tf32.tf32.f32 " \
        "{%0,%1,%2,%3}, {%4,%5,%6,%7}, {%8,%9}, {%0,%1,%2,%3};" \
        : "+f"((d)[0]), "+f"((d)[1]), "+f"((d)[2]), "+f"((d)[3]) \
        : "r"((a)[0]), "r"((a)[1]), "r"((a)[2]), "r"((a)[3]), "r"(b0v), "r"(b1v))

__device__ __forceinline__ float tf32_round(float v) {
    uint32_t r;
    asm("cvt.rna.tf32.f32 %0, %1;" : "=r"(r) : "f"(v));
    return __uint_as_float(r);
}

// ---------------------------------------------------------------------------
// scratch (device globals; no allocation allowed)
// ---------------------------------------------------------------------------
__device__ float g_q [MR * HD];
__device__ float g_v [MR * HD];
__device__ float g_u [MR * HD];
__device__ float g_o [MR * HD];
__device__ float g_kv[SPLITS * Bn * HEADS * DHd * DHd];
__device__ float g_xr [MR * Ein];           // tf32-rounded x
__device__ float g_lnr[MR * HD];            // tf32-rounded ln*u
__device__ float g_wqk_t[HD * Ein];         // [N][K] transposed, tf32-rounded
__device__ float g_wv_t [HD * Ein];
__device__ float g_wu_t [HD * Ein];
__device__ float g_wo_t [Ein * HD];

// ---------------------------------------------------------------------------
// tf32 mma.sync GEMM: C[M,2048] = act( A[M,2048] @ Bt[N,K]^T + bias )
// BM=128 BN=128 BK=32, 4-stage cp.async, 8 warps (2m x 4n), warp tile 64x32.
// ---------------------------------------------------------------------------
#define BM 128
#define BN 128
#define BK 32
#define STAGES 4
#define AST_BYTES (BM * BK * 4)                  // 16384
#define STG_BYTES (AST_BYTES + BN * BK * 4)      // 32768
#define GEMM_SMEM (STAGES * STG_BYTES)           // 131072
#define NIT (2048 / BK)                          // 64

// ACT: 0 none, 1 elu, 2 silu
template<int ACT>
__global__ void __launch_bounds__(256) gemm_tf32(
    const float* __restrict__ A, const float* __restrict__ Bt,
    const float* __restrict__ bias, float* __restrict__ C)
{
    extern __shared__ char smem[];
    const uint32_t sb = smem_u32(smem);
    const int tid = threadIdx.x;
    const int m0 = blockIdx.y * BM;
    const int n0 = blockIdx.x * BN;

    const int lane = tid & 31, w = tid >> 5;
    const int wm = (w >> 2) * 64;        // warp m offset in tile
    const int wn = (w & 3) * 32;         // warp n offset in tile
    const int mi = lane >> 3, rowin = lane & 7;

    // ldmatrix per-lane address components (relative to stage base)
    // A: matrices {rows 0-7/c0-3, rows 8-15/c0-3, rows 0-7/c4-7, rows 8-15/c4-7}
    uint32_t aoff[4]; int arb[4];
    const int au = mi >> 1, aro = (mi & 1) << 3;
#pragma unroll
    for (int mt = 0; mt < 4; mt++) {
        int r = wm + mt * 16 + aro + rowin;
        aoff[mt] = r * 128;
        arb[mt] = r & 7;
    }
    // B: matrices {n0-7/k0-3, n0-7/k4-7, n8-15/k0-3, n8-15/k4-7}
    uint32_t boff[2]; int brb[2];
    const int bu = mi & 1, bro = (mi >> 1) << 3;
#pragma unroll
    for (int p = 0; p < 2; p++) {
        int r = wn + p * 16 + bro + rowin;
        boff[p] = AST_BYTES + r * 128;
        brb[p] = r & 7;
    }

    float acc[4][4][4] = {};

    // -------- pipeline --------
#pragma unroll
    for (int s = 0; s < STAGES - 1; s++) {
        const uint32_t st = sb + s * STG_BYTES;
        const int k0 = s * BK;
#pragma unroll
        for (int i = 0; i < 4; i++) {
            int idx = tid + i * 256;
            int r = idx >> 3, u = idx & 7;
            CP16(st + r * 128 + ((u ^ (r & 7)) << 4),
                 A + (size_t)(m0 + r) * 2048 + k0 + u * 4);
        }
#pragma unroll
        for (int i = 0; i < 4; i++) {
            int idx = tid + i * 256;
            int r = idx >> 3, u = idx & 7;
            CP16(st + AST_BYTES + r * 128 + ((u ^ (r & 7)) << 4),
                 Bt + (size_t)(n0 + r) * 2048 + k0 + u * 4);
        }
        CP_COMMIT();
    }

    for (int it = 0; it < NIT; it++) {
        CP_WAIT(STAGES - 2);
        __syncthreads();
        const uint32_t st = sb + (it & (STAGES - 1)) * STG_BYTES;
#pragma unroll
        for (int ks = 0; ks < 4; ks++) {
            uint32_t afr[4][4];
#pragma unroll
            for (int mt = 0; mt < 4; mt++) {
                uint32_t ad = st + aoff[mt] + (uint32_t)(((2 * ks + au) ^ arb[mt]) << 4);
                LDMX4(afr[mt], ad);
            }
            uint32_t bfr[2][4];
#pragma unroll
            for (int p = 0; p < 2; p++) {
                uint32_t bd = st + boff[p] + (uint32_t)(((2 * ks + bu) ^ brb[p]) << 4);
                LDMX4(bfr[p], bd);
            }
#pragma unroll
            for (int mt = 0; mt < 4; mt++)
#pragma unroll
                for (int nt = 0; nt < 4; nt++)
                    MMA_TF32(acc[mt][nt], afr[mt],
                             bfr[nt >> 1][(nt & 1) * 2], bfr[nt >> 1][(nt & 1) * 2 + 1]);
        }
        const int nx = it + STAGES - 1;
        if (nx < NIT) {
            const uint32_t st2 = sb + (nx & (STAGES - 1)) * STG_BYTES;
            const int k0 = nx * BK;
#pragma unroll
            for (int i = 0; i < 4; i++) {
                int idx = tid + i * 256;
                int r = idx >> 3, u = idx & 7;
                CP16(st2 + r * 128 + ((u ^ (r & 7)) << 4),
                     A + (size_t)(m0 + r) * 2048 + k0 + u * 4);
            }
#pragma unroll
            for (int i = 0; i < 4; i++) {
                int idx = tid + i * 256;
                int r = idx >> 3, u = idx & 7;
                CP16(st2 + AST_BYTES + r * 128 + ((u ^ (r & 7)) << 4),
                     Bt + (size_t)(n0 + r) * 2048 + k0 + u * 4);
            }
            CP_COMMIT();
        }
    }

    // -------- epilogue --------
    const int g = lane >> 2, t = lane & 3;
#pragma unroll
    for (int mt = 0; mt < 4; mt++) {
#pragma unroll
        for (int nt = 0; nt < 4; nt++) {
            const int rm = m0 + wm + mt * 16 + g;
            const int cn = n0 + wn + nt * 8 + 2 * t;
            const float b0 = bias[cn], b1 = bias[cn + 1];
            float v0 = acc[mt][nt][0] + b0;
            float v1 = acc[mt][nt][1] + b1;
            float v2 = acc[mt][nt][2] + b0;
            float v3 = acc[mt][nt][3] + b1;
            if (ACT == 1) {
                v0 = v0 > 0.f ? v0 : (expf(v0) - 1.f);
                v1 = v1 > 0.f ? v1 : (expf(v1) - 1.f);
                v2 = v2 > 0.f ? v2 : (expf(v2) - 1.f);
                v3 = v3 > 0.f ? v3 : (expf(v3) - 1.f);
            } else if (ACT == 2) {
                v0 = v0 / (1.f + expf(-v0));
                v1 = v1 / (1.f + expf(-v1));
                v2 = v2 / (1.f + expf(-v2));
                v3 = v3 / (1.f + expf(-v3));
            }
            *(float2*)(C + (size_t)rm * 2048 + cn) = make_float2(v0, v1);
            *(float2*)(C + (size_t)(rm + 8) * 2048 + cn) = make_float2(v2, v3);
        }
    }
}

// ---------------------------------------------------------------------------
// prep kernels
// ---------------------------------------------------------------------------
__global__ void round_kernel(const float* __restrict__ x, float* __restrict__ y, int n4) {
    int i = blockIdx.x * blockDim.x + threadIdx.x;
    if (i >= n4) return;
    float4 v = ((const float4*)x)[i];
    v.x = tf32_round(v.x); v.y = tf32_round(v.y);
    v.z = tf32_round(v.z); v.w = tf32_round(v.w);
    ((float4*)y)[i] = v;
}

// W[K,N] fp32 -> T[N,K] tf32-rounded fp32 (K=N=2048)
__global__ void trans_round_kernel(const float* __restrict__ W, float* __restrict__ T) {
    __shared__ float tile[32][33];
    const int k0 = blockIdx.y * 32, n0 = blockIdx.x * 32;
    const int tx = threadIdx.x, ty = threadIdx.y;
#pragma unroll
    for (int i = 0; i < 32; i += 8)
        tile[ty + i][tx] = W[(size_t)(k0 + ty + i) * 2048 + n0 + tx];
    __syncthreads();
#pragma unroll
    for (int i = 0; i < 32; i += 8)
        T[(size_t)(n0 + ty + i) * 2048 + k0 + tx] = tf32_round(tile[tx][ty + i]);
}

// ---------------------------------------------------------------------------
// kv = q^T v per (b,h), split over sequence (fp32 SIMT)
// ---------------------------------------------------------------------------
__global__ void kv_kernel() {
    __shared__ float qs[16][128];
    __shared__ float vs[16][128];
    const int bh = blockIdx.x;
    const int b = bh / HEADS, h = bh % HEADS;
    const int split = blockIdx.y;
    const int chunk = SEQ / SPLITS;
    const int n0 = split * chunk;
    const int tid = threadIdx.x;
    const int tx = tid & 15, ty = tid >> 4;
    const size_t base = (size_t)(b * SEQ) * HD + h * DHd;

    float acc[8][8] = {};
    for (int nt = 0; nt < chunk; nt += 16) {
#pragma unroll
        for (int l = 0; l < 2; l++) {
            const int idx = tid + l * 256;
            const int r = idx >> 5;
            const int c = (idx & 31) * 4;
            const size_t off = base + (size_t)(n0 + nt + r) * HD + c;
            *(float4*)&qs[r][c] = *(const float4*)(g_q + off);
            *(float4*)&vs[r][c] = *(const float4*)(g_v + off);
        }
        __syncthreads();
#pragma unroll
        for (int kk = 0; kk < 16; kk++) {
            float rq[8], rv[8];
#pragma unroll
            for (int i = 0; i < 8; i++) rq[i] = qs[kk][ty * 8 + i];
#pragma unroll
            for (int j = 0; j < 8; j++) rv[j] = vs[kk][tx * 8 + j];
#pragma unroll
            for (int i = 0; i < 8; i++)
#pragma unroll
                for (int j = 0; j < 8; j++)
                    acc[i][j] += rq[i] * rv[j];
        }
        __syncthreads();
    }
    float* kvp = g_kv + ((size_t)split * Bn * HEADS + bh) * DHd * DHd;
#pragma unroll
    for (int i = 0; i < 8; i++)
#pragma unroll
        for (int j = 0; j < 8; j++)
            kvp[(ty * 8 + i) * DHd + tx * 8 + j] = acc[i][j];
}

// ---------------------------------------------------------------------------
// out = q @ kv per (b,h) (fp32 SIMT, sums 4 split slices)
// ---------------------------------------------------------------------------
__global__ void out_kernel() {
    __shared__ float As[16][64];
    __shared__ float Bs[16][128];
    const int m0 = blockIdx.x * 64;
    const int h = blockIdx.y;
    const int b = m0 / SEQ;
    const int tid = threadIdx.x;
    const int tx = tid & 15, ty = tid >> 4;
    const size_t kvoff = (size_t)(b * HEADS + h) * DHd * DHd;
    const size_t kvstride = (size_t)Bn * HEADS * DHd * DHd;

    float acc[4][8] = {};
    const int a_r = tid >> 2;
    const int a_s = (tid & 3) * 4;

    for (int k0 = 0; k0 < DHd; k0 += 16) {
        float4 av = *(const float4*)(g_q + (size_t)(m0 + a_r) * HD + h * DHd + k0 + a_s);
        As[a_s + 0][a_r] = av.x;
        As[a_s + 1][a_r] = av.y;
        As[a_s + 2][a_r] = av.z;
        As[a_s + 3][a_r] = av.w;
#pragma unroll
        for (int l = 0; l < 2; l++) {
            const int idx = tid + l * 256;
            const int r = idx >> 5;
            const int c = (idx & 31) * 4;
            const size_t boff = kvoff + (size_t)(k0 + r) * DHd + c;
            float4 s0 = *(const float4*)(g_kv + boff);
            float4 s1 = *(const float4*)(g_kv + boff + kvstride);
            float4 s2 = *(const float4*)(g_kv + boff + 2 * kvstride);
            float4 s3 = *(const float4*)(g_kv + boff + 3 * kvstride);
            float4 sum;
            sum.x = (s0.x + s1.x) + (s2.x + s3.x);
            sum.y = (s0.y + s1.y) + (s2.y + s3.y);
            sum.z = (s0.z + s1.z) + (s2.z + s3.z);
            sum.w = (s0.w + s1.w) + (s2.w + s3.w);
            *(float4*)&Bs[r][c] = sum;
        }
        __syncthreads();
#pragma unroll
        for (int kk = 0; kk < 16; kk++) {
            float ra[4], rb[8];
#pragma unroll
            for (int i = 0; i < 4; i++) ra[i] = As[kk][ty * 4 + i];
#pragma unroll
            for (int j = 0; j < 8; j++) rb[j] = Bs[kk][tx * 8 + j];
#pragma unroll
            for (int i = 0; i < 4; i++)
#pragma unroll
                for (int j = 0; j < 8; j++)
                    acc[i][j] += ra[i] * rb[j];
        }
        __syncthreads();
    }
#pragma unroll
    for (int i = 0; i < 4; i++)
#pragma unroll
        for (int j = 0; j < 8; j++)
            g_o[(size_t)(m0 + ty * 4 + i) * HD + h * DHd + tx * 8 + j] = acc[i][j];
}

// ---------------------------------------------------------------------------
// LayerNorm over HD, * gate u, emit tf32-rounded fp32 for final GEMM
// ---------------------------------------------------------------------------
__global__ void ln_mul_kernel(const float* __restrict__ lng, const float* __restrict__ lnb) {
    __shared__ float buf[HD];
    __shared__ float red[256];
    const int row = blockIdx.x;
    const int tid = threadIdx.x;
    const float* orow = g_o + (size_t)row * HD;
    const float* urow = g_u + (size_t)row * HD;

    float s = 0.f;
    for (int c = tid; c < HD; c += 256) { float v = orow[c]; buf[c] = v; s += v; }
    red[tid] = s; __syncthreads();
    for (int off = 128; off; off >>= 1) { if (tid < off) red[tid] += red[tid + off]; __syncthreads(); }
    const float mean = red[0] * (1.f / HD);
    __syncthreads();

    float s2 = 0.f;
    for (int c = tid; c < HD; c += 256) { float d = buf[c] - mean; s2 += d * d; }
    red[tid] = s2; __syncthreads();
    for (int off = 128; off; off >>= 1) { if (tid < off) red[tid] += red[tid + off]; __syncthreads(); }
    const float rstd = rsqrtf(red[0] * (1.f / HD) + 1e-5f);

    for (int c = tid; c < HD; c += 256) {
        float v = ((buf[c] - mean) * rstd * lng[c] + lnb[c]) * urow[c];
        g_lnr[(size_t)row * HD + c] = tf32_round(v);
    }
}

// ---------------------------------------------------------------------------
// launch
// ---------------------------------------------------------------------------
extern "C" void kernel_launch(void* const* d_in, const int* in_sizes, int n_in,
                              void* d_out, int out_size) {
    const float* x   = (const float*)d_in[0];
    const float* Wqk = (const float*)d_in[1];
    const float* bqk = (const float*)d_in[2];
    const float* Wv  = (const float*)d_in[3];
    const float* bv  = (const float*)d_in[4];
    const float* Wu  = (const float*)d_in[5];
    const float* bu  = (const float*)d_in[6];
    const float* Wo  = (const float*)d_in[7];
    const float* bo  = (const float*)d_in[8];
    const float* lng = (const float*)d_in[9];
    const float* lnb = (const float*)d_in[10];
    float* out = (float*)d_out;

    float *pq, *pv, *pu, *pxr, *plnr, *pwqk, *pwv, *pwu, *pwo;
    cudaGetSymbolAddress((void**)&pq, g_q);
    cudaGetSymbolAddress((void**)&pv, g_v);
    cudaGetSymbolAddress((void**)&pu, g_u);
    cudaGetSymbolAddress((void**)&pxr, g_xr);
    cudaGetSymbolAddress((void**)&plnr, g_lnr);
    cudaGetSymbolAddress((void**)&pwqk, g_wqk_t);
    cudaGetSymbolAddress((void**)&pwv, g_wv_t);
    cudaGetSymbolAddress((void**)&pwu, g_wu_t);
    cudaGetSymbolAddress((void**)&pwo, g_wo_t);

    cudaFuncSetAttribute(gemm_tf32<0>, cudaFuncAttributeMaxDynamicSharedMemorySize, GEMM_SMEM);
    cudaFuncSetAttribute(gemm_tf32<1>, cudaFuncAttributeMaxDynamicSharedMemorySize, GEMM_SMEM);
    cudaFuncSetAttribute(gemm_tf32<2>, cudaFuncAttributeMaxDynamicSharedMemorySize, GEMM_SMEM);

    // prep: round x; transpose+round weights
    {
        int n4 = MR * Ein / 4;
        round_kernel<<<(n4 + 255) / 256, 256>>>(x, pxr, n4);
        dim3 tb(32, 8), tg(64, 64);
        trans_round_kernel<<<tg, tb>>>(Wqk, pwqk);
        trans_round_kernel<<<tg, tb>>>(Wv, pwv);
        trans_round_kernel<<<tg, tb>>>(Wu, pwu);
        trans_round_kernel<<<tg, tb>>>(Wo, pwo);
    }

    dim3 ggrid(HD / BN, MR / BM);    // (16, 128)

    // q = elu(x@Wqk + bqk); v = silu(x@Wv + bv); u = silu(x@Wu + bu)
    gemm_tf32<1><<<ggrid, 256, GEMM_SMEM>>>(pxr, pwqk, bqk, pq);
    gemm_tf32<2><<<ggrid, 256, GEMM_SMEM>>>(pxr, pwv, bv, pv);
    gemm_tf32<2><<<ggrid, 256, GEMM_SMEM>>>(pxr, pwu, bu, pu);

    // linear attention
    kv_kernel<<<dim3(Bn * HEADS, SPLITS), 256>>>();
    out_kernel<<<dim3(MR / 64, HEADS), 256>>>();

    // LN * gate -> tf32-rounded
    ln_mul_kernel<<<MR, 256>>>(lng, lnb);

    // y = ln_out @ Wo + bo
    gemm_tf32<0><<<ggrid, 256, GEMM_SMEM>>>(plnr, pwo, bo, out);
}